// round 15
// baseline (speedup 1.0000x reference)
#include <cuda_runtime.h>
#include <cuda_fp16.h>

#define SS 512
#define CC 64
#define VV 4
#define NFACES 400000
#define NP (SS*SS)             // 262144 pixels per view
#define VW ((NFACES+31)/32)    // 12500 words per view bitmask
#define NMAX 200000

// Scratch (static device allocations; no runtime mallocs allowed)
__device__ __align__(128) __half g_featT[(size_t)VV * NP * CC]; // 128 MiB, channel-last fp16
__device__ unsigned g_vis[VV * VW];      // per-view face visibility bitmask
__device__ float    g_P[VV * 12];        // fused camera: rows of K@R (3x3) + K@t, [r*4+c]
__device__ int4     g_moff[NMAX * VV];   // 4 corner offsets (uint4 units), dead views -> 0
__device__ float4   g_mw[NMAX * VV];     // 4 corner weights (mask-folded, normalized)

// ---------------------------------------------------------------------------
// 1. clear visibility bitmask
__global__ void clear_vis_kernel() {
    int i = blockIdx.x * blockDim.x + threadIdx.x;
    if (i < VV * VW) g_vis[i] = 0u;
}

// 2. scatter pix_to_face into visibility bitmask
__global__ void scatter_vis_kernel(const int* __restrict__ p2f) {
    int i = blockIdx.x * blockDim.x + threadIdx.x;
    if (i >= VV * NP) return;
    int f = __ldcs(&p2f[i]);
    if (f >= 0) {
        int v = i >> 18; // i / NP
        atomicOr(&g_vis[v * VW + (f >> 5)], 1u << (f & 31));
    }
}

// 3. fuse cameras: P = K@R, q = K@t
__global__ void cam_kernel(const float* __restrict__ Rm, const float* __restrict__ tm,
                           const float* __restrict__ Km) {
    int v = threadIdx.x;
    if (v >= VV) return;
    const float* R = Rm + v * 9;
    const float* t = tm + v * 3;
    const float* K = Km + v * 9;
    #pragma unroll
    for (int r = 0; r < 3; r++) {
        #pragma unroll
        for (int c = 0; c < 3; c++)
            g_P[v * 12 + r * 4 + c] = K[r*3+0]*R[0*3+c] + K[r*3+1]*R[1*3+c] + K[r*3+2]*R[2*3+c];
        g_P[v * 12 + r * 4 + 3] = K[r*3+0]*t[0] + K[r*3+1]*t[1] + K[r*3+2]*t[2];
    }
}

// shared projection: raw pixel-space xy for (vertex, view)
__device__ __forceinline__ void proj_xy(float px, float py, float pz, int v,
                                        float* x, float* y) {
    const float* P = g_P + v * 12;
    float u  = P[0]*px + P[1]*py + P[2] *pz + P[3];
    float w_ = P[4]*px + P[5]*py + P[6] *pz + P[7];
    float zz = P[8]*px + P[9]*py + P[10]*pz + P[11];
    float rz = __frcp_rn(zz);
    *x = u * rz; *y = w_ * rz;
}

// 4. per-vertex metadata (runs on side stream, hidden under transpose):
//    projection, bilinear corners, visibility-folded weights; dead views -> offset 0.
__global__ __launch_bounds__(256) void meta_kernel(
    const float* __restrict__ verts, const int* __restrict__ faces, int n)
{
    int i = blockIdx.x * blockDim.x + threadIdx.x;
    if (i >= n) return;
    float px = verts[3*i], py = verts[3*i+1], pz = verts[3*i+2];
    int f = faces[i];

    int m[VV]; int msum = 0;
    #pragma unroll
    for (int v = 0; v < VV; v++) {
        m[v] = (g_vis[v * VW + (f >> 5)] >> (f & 31)) & 1;
        msum += m[v];
    }
    float inv = 1.0f / (float)(msum ? msum : VV);

    #pragma unroll
    for (int v = 0; v < VV; v++) {
        float bw = (msum ? (float)m[v] : 1.0f) * inv;

        float x, y;
        proj_xy(px, py, pz, v, &x, &y);
        float x0f = floorf(x), y0f = floorf(y);
        float x1f = x0f + 1.0f, y1f = y0f + 1.0f;
        float wx1 = x - x0f, wx0 = 1.0f - wx1;
        float wy1 = y - y0f, wy0 = 1.0f - wy1;

        bool vx0 = (x0f >= 0.0f) && (x0f <= (float)(SS-1));
        bool vx1 = (x1f >= 0.0f) && (x1f <= (float)(SS-1));
        bool vy0 = (y0f >= 0.0f) && (y0f <= (float)(SS-1));
        bool vy1 = (y1f >= 0.0f) && (y1f <= (float)(SS-1));

        int xc0 = (int)fminf(fmaxf(x0f, 0.0f), (float)(SS-1));
        int xc1 = (int)fminf(fmaxf(x1f, 0.0f), (float)(SS-1));
        int yc0 = (int)fminf(fmaxf(y0f, 0.0f), (float)(SS-1));
        int yc1 = (int)fminf(fmaxf(y1f, 0.0f), (float)(SS-1));

        float4 wq;
        wq.x = bw * wx0 * wy0 * (float)(vx0 && vy0);
        wq.y = bw * wx1 * wy0 * (float)(vx1 && vy0);
        wq.z = bw * wx0 * wy1 * (float)(vx0 && vy1);
        wq.w = bw * wx1 * wy1 * (float)(vx1 && vy1);

        bool live = (wq.x + wq.y + wq.z + wq.w) != 0.0f;
        int baseV = v * NP;
        g_moff[i * VV + v] = live ? make_int4((baseV + yc0 * SS + xc0) * 8,
                                              (baseV + yc0 * SS + xc1) * 8,
                                              (baseV + yc1 * SS + xc0) * 8,
                                              (baseV + yc1 * SS + xc1) * 8)
                                  : make_int4(0, 0, 0, 0);
        g_mw[i * VV + v] = wq;
    }
}

// 5. transpose feature [V,C,S,S] fp32 -> [V,S,S,C] fp16 (EXACT proven R7 version:
//    32-px tiles, 8KB smem, high occupancy — measured at the LTS cap)
__global__ __launch_bounds__(256) void transpose_feat_kernel(const float* __restrict__ feat) {
    __shared__ float tile[CC][33];
    int v  = blockIdx.y;
    int p0 = blockIdx.x * 32;
    const float* in = feat + (size_t)v * CC * NP + p0;
    int tx = threadIdx.x & 31, tw = threadIdx.x >> 5;
    #pragma unroll
    for (int j = 0; j < 8; j++) {
        int r = tw * 8 + j;
        tile[r][tx] = __ldcs(&in[(size_t)r * NP + tx]);
    }
    __syncthreads();
    __half2* out = ((__half2*)g_featT) + ((size_t)v * NP + p0) * 32;
    int cp = tx;
    int pb = tw;
    #pragma unroll
    for (int k = 0; k < 4; k++) {
        int p = pb + k * 8;
        __half2 h = __floats2half2_rn(tile[2*cp][p], tile[2*cp+1][p]);
        out[(size_t)p * 32 + cp] = h;
    }
}

// accumulate 8 fp16 channels (one uint4) with weight w into acc[8]
__device__ __forceinline__ void accum8(float* acc, uint4 q, float w) {
    __half2 h0 = *(__half2*)&q.x, h1 = *(__half2*)&q.y;
    __half2 h2 = *(__half2*)&q.z, h3 = *(__half2*)&q.w;
    float2 f0 = __half22float2(h0), f1 = __half22float2(h1);
    float2 f2 = __half22float2(h2), f3 = __half22float2(h3);
    acc[0] = fmaf(w, f0.x, acc[0]); acc[1] = fmaf(w, f0.y, acc[1]);
    acc[2] = fmaf(w, f1.x, acc[2]); acc[3] = fmaf(w, f1.y, acc[3]);
    acc[4] = fmaf(w, f2.x, acc[4]); acc[5] = fmaf(w, f2.y, acc[5]);
    acc[6] = fmaf(w, f3.x, acc[6]); acc[7] = fmaf(w, f3.y, acc[7]);
}

// 6. lean gather: 32 vertices per 256-thread block.
//    Prologue: coalesced copy of precomputed meta (4KB) into smem — no math,
//    no dependent-load chain. Phase 2: branch-free batched loads (R14).
__global__ __launch_bounds__(256) void gather_kernel(float* __restrict__ out, int n)
{
    __shared__ int4   s_off[32][VV];
    __shared__ float4 s_w[32][VV];

    int vb = blockIdx.x * 32;
    int t  = threadIdx.x;

    {
        int e = t & 127;          // entry 0..127 = (j, v)
        int j = e >> 2, v = e & 3;
        int idx = (vb + j) * VV + v;
        if (vb + j < n) {
            if (t < 128) s_off[j][v] = g_moff[idx];
            else         s_w[j][v]   = g_mw[idx];
        }
    }
    __syncthreads();

    int j = t >> 3;
    int i = vb + j;
    int ck = t & 7;           // channel chunk (8 channels)
    if (i >= n) return;

    const uint4* B = (const uint4*)g_featT;
    float acc[8] = {0.f,0.f,0.f,0.f,0.f,0.f,0.f,0.f};
    #pragma unroll
    for (int vp = 0; vp < 2; vp++) {
        uint4 r[8];
        int4   o0 = s_off[j][vp*2],   o1 = s_off[j][vp*2+1];
        float4 w0 = s_w[j][vp*2],     w1 = s_w[j][vp*2+1];
        r[0] = B[o0.x + ck]; r[1] = B[o0.y + ck];
        r[2] = B[o0.z + ck]; r[3] = B[o0.w + ck];
        r[4] = B[o1.x + ck]; r[5] = B[o1.y + ck];
        r[6] = B[o1.z + ck]; r[7] = B[o1.w + ck];
        accum8(acc, r[0], w0.x); accum8(acc, r[1], w0.y);
        accum8(acc, r[2], w0.z); accum8(acc, r[3], w0.w);
        accum8(acc, r[4], w1.x); accum8(acc, r[5], w1.y);
        accum8(acc, r[6], w1.z); accum8(acc, r[7], w1.w);
    }
    float4* O = (float4*)(out + (size_t)i * CC + ck * 8);
    __stcs(O,     make_float4(acc[0], acc[1], acc[2], acc[3]));
    __stcs(O + 1, make_float4(acc[4], acc[5], acc[6], acc[7]));
}

// ---------------------------------------------------------------------------
// Side stream + fork/join events: created once (first call is the uncaptured
// correctness run); reused on every call so captured work is identical.
static cudaStream_t g_side = nullptr;
static cudaEvent_t  g_evFork = nullptr, g_evJoin = nullptr;

extern "C" void kernel_launch(void* const* d_in, const int* in_sizes, int n_in,
                              void* d_out, int out_size) {
    const float* verts = nullptr;
    const int*   faces = nullptr;
    const float* Rm = nullptr, *tm = nullptr, *Km = nullptr, *feat = nullptr;
    const int*   p2f = nullptr;
    int n36 = 0;
    for (int i = 0; i < n_in; i++) {
        int s = in_sizes[i];
        if      (s == 600000)   verts = (const float*)d_in[i];
        else if (s == 200000)   faces = (const int*)d_in[i];
        else if (s == 36)       { if (n36++ == 0) Rm = (const float*)d_in[i]; else Km = (const float*)d_in[i]; }
        else if (s == 12)       tm = (const float*)d_in[i];
        else if (s == 67108864) feat = (const float*)d_in[i];
        else if (s == 1048576)  p2f = (const int*)d_in[i];
    }
    int n = 200000;

    if (g_side == nullptr) {
        cudaStreamCreateWithFlags(&g_side, cudaStreamNonBlocking);
        cudaEventCreateWithFlags(&g_evFork, cudaEventDisableTiming);
        cudaEventCreateWithFlags(&g_evJoin, cudaEventDisableTiming);
    }

    // fork: side branch = visibility + camera + per-vertex metadata
    // (all independent of the feature tensor; hidden under the transpose)
    cudaEventRecord(g_evFork, 0);
    cudaStreamWaitEvent(g_side, g_evFork, 0);
    clear_vis_kernel<<<(VV * VW + 255) / 256, 256, 0, g_side>>>();
    scatter_vis_kernel<<<(VV * NP + 255) / 256, 256, 0, g_side>>>(p2f);
    cam_kernel<<<1, 32, 0, g_side>>>(Rm, tm, Km);
    meta_kernel<<<(n + 255) / 256, 256, 0, g_side>>>(verts, faces, n);
    cudaEventRecord(g_evJoin, g_side);

    // main branch: full feature transpose (the long pole)
    transpose_feat_kernel<<<dim3(NP / 32, VV), 256>>>(feat);

    // join: gather needs featT + meta
    cudaStreamWaitEvent(0, g_evJoin, 0);
    gather_kernel<<<(n + 31) / 32, 256>>>((float*)d_out, n);
}

// round 16
// speedup vs baseline: 1.0653x; 1.0653x over previous
#include <cuda_runtime.h>
#include <cuda_fp16.h>

#define SS 512
#define CC 64
#define VV 4
#define NFACES 400000
#define NP (SS*SS)             // 262144 pixels per view
#define VW ((NFACES+31)/32)    // 12500 words per view bitmask
#define NMAX 200000

// Scratch (static device allocations; no runtime mallocs allowed)
__device__ __align__(128) __half g_featT[(size_t)VV * NP * CC]; // 128 MiB, channel-last fp16
__device__ unsigned g_vis[VV * VW];      // per-view face visibility bitmask
__device__ float    g_P[VV * 12];        // fused camera: rows of K@R (3x3) + K@t, [r*4+c]

// ---------------------------------------------------------------------------
// 1. clear visibility bitmask
__global__ void clear_vis_kernel() {
    int i = blockIdx.x * blockDim.x + threadIdx.x;
    if (i < VV * VW) g_vis[i] = 0u;
}

// 2. scatter pix_to_face into visibility bitmask
__global__ void scatter_vis_kernel(const int* __restrict__ p2f) {
    int i = blockIdx.x * blockDim.x + threadIdx.x;
    if (i >= VV * NP) return;
    int f = __ldcs(&p2f[i]);
    if (f >= 0) {
        int v = i >> 18; // i / NP
        atomicOr(&g_vis[v * VW + (f >> 5)], 1u << (f & 31));
    }
}

// 3. fuse cameras: P = K@R, q = K@t
__global__ void cam_kernel(const float* __restrict__ Rm, const float* __restrict__ tm,
                           const float* __restrict__ Km) {
    int v = threadIdx.x;
    if (v >= VV) return;
    const float* R = Rm + v * 9;
    const float* t = tm + v * 3;
    const float* K = Km + v * 9;
    #pragma unroll
    for (int r = 0; r < 3; r++) {
        #pragma unroll
        for (int c = 0; c < 3; c++)
            g_P[v * 12 + r * 4 + c] = K[r*3+0]*R[0*3+c] + K[r*3+1]*R[1*3+c] + K[r*3+2]*R[2*3+c];
        g_P[v * 12 + r * 4 + 3] = K[r*3+0]*t[0] + K[r*3+1]*t[1] + K[r*3+2]*t[2];
    }
}

// 4. transpose feature [V,C,S,S] fp32 -> [V,S,S,C] fp16 (proven R7 version:
//    32-px tiles, 8KB smem, high occupancy — measured at the LTS cap)
__global__ __launch_bounds__(256) void transpose_feat_kernel(const float* __restrict__ feat) {
    __shared__ float tile[CC][33];
    int v  = blockIdx.y;
    int p0 = blockIdx.x * 32;
    const float* in = feat + (size_t)v * CC * NP + p0;
    int tx = threadIdx.x & 31, tw = threadIdx.x >> 5;
    #pragma unroll
    for (int j = 0; j < 8; j++) {
        int r = tw * 8 + j;
        tile[r][tx] = __ldcs(&in[(size_t)r * NP + tx]);
    }
    __syncthreads();
    __half2* out = ((__half2*)g_featT) + ((size_t)v * NP + p0) * 32;
    int cp = tx;
    int pb = tw;
    #pragma unroll
    for (int k = 0; k < 4; k++) {
        int p = pb + k * 8;
        __half2 h = __floats2half2_rn(tile[2*cp][p], tile[2*cp+1][p]);
        out[(size_t)p * 32 + cp] = h;
    }
}

// shared projection: raw pixel-space xy for (vertex, view)
__device__ __forceinline__ void proj_xy(float px, float py, float pz, int v,
                                        float* x, float* y) {
    const float* P = g_P + v * 12;
    float u  = P[0]*px + P[1]*py + P[2] *pz + P[3];
    float w_ = P[4]*px + P[5]*py + P[6] *pz + P[7];
    float zz = P[8]*px + P[9]*py + P[10]*pz + P[11];
    float rz = __frcp_rn(zz);
    *x = u * rz; *y = w_ * rz;
}

// accumulate 8 fp16 channels (one uint4) with weight w into acc[8]
__device__ __forceinline__ void accum8(float* acc, uint4 q, float w) {
    __half2 h0 = *(__half2*)&q.x, h1 = *(__half2*)&q.y;
    __half2 h2 = *(__half2*)&q.z, h3 = *(__half2*)&q.w;
    float2 f0 = __half22float2(h0), f1 = __half22float2(h1);
    float2 f2 = __half22float2(h2), f3 = __half22float2(h3);
    acc[0] = fmaf(w, f0.x, acc[0]); acc[1] = fmaf(w, f0.y, acc[1]);
    acc[2] = fmaf(w, f1.x, acc[2]); acc[3] = fmaf(w, f1.y, acc[3]);
    acc[4] = fmaf(w, f2.x, acc[4]); acc[5] = fmaf(w, f2.y, acc[5]);
    acc[6] = fmaf(w, f3.x, acc[6]); acc[7] = fmaf(w, f3.y, acc[7]);
}

// 5. fused meta + gather (proven R14 version): 32 vertices per 256-thread block.
//    Phase 1 (128 threads): per-(vertex,view) metadata into smem; dead views
//    get offset 0 (warp-uniform L1-hot broadcast line) with weight 0.
//    Phase 2 (all threads): branch-free, 2 batches of 8 independent uint4 loads.
__global__ __launch_bounds__(256) void gather_kernel(
    float* __restrict__ out,
    const float* __restrict__ verts, const int* __restrict__ faces, int n)
{
    __shared__ int4   s_off[32][VV];
    __shared__ float4 s_w[32][VV];

    int vb = blockIdx.x * 32;
    int t  = threadIdx.x;

    if (t < 128) {
        int j = t >> 2, v = t & 3;
        int i = vb + j;
        if (i < n) {
            float px = verts[3*i], py = verts[3*i+1], pz = verts[3*i+2];
            int f = faces[i];
            int msum = 0, mv = 0;
            #pragma unroll
            for (int vv = 0; vv < VV; vv++) {
                int b = (g_vis[vv * VW + (f >> 5)] >> (f & 31)) & 1;
                msum += b;
                if (vv == v) mv = b;
            }
            float inv = 1.0f / (float)(msum ? msum : VV);
            float bw  = (msum ? (float)mv : 1.0f) * inv;

            float x, y;
            proj_xy(px, py, pz, v, &x, &y);
            float x0f = floorf(x), y0f = floorf(y);
            float x1f = x0f + 1.0f, y1f = y0f + 1.0f;
            float wx1 = x - x0f, wx0 = 1.0f - wx1;
            float wy1 = y - y0f, wy0 = 1.0f - wy1;

            bool vx0 = (x0f >= 0.0f) && (x0f <= (float)(SS-1));
            bool vx1 = (x1f >= 0.0f) && (x1f <= (float)(SS-1));
            bool vy0 = (y0f >= 0.0f) && (y0f <= (float)(SS-1));
            bool vy1 = (y1f >= 0.0f) && (y1f <= (float)(SS-1));

            int xc0 = (int)fminf(fmaxf(x0f, 0.0f), (float)(SS-1));
            int xc1 = (int)fminf(fmaxf(x1f, 0.0f), (float)(SS-1));
            int yc0 = (int)fminf(fmaxf(y0f, 0.0f), (float)(SS-1));
            int yc1 = (int)fminf(fmaxf(y1f, 0.0f), (float)(SS-1));

            float4 wq;
            wq.x = bw * wx0 * wy0 * (float)(vx0 && vy0);
            wq.y = bw * wx1 * wy0 * (float)(vx1 && vy0);
            wq.z = bw * wx0 * wy1 * (float)(vx0 && vy1);
            wq.w = bw * wx1 * wy1 * (float)(vx1 && vy1);

            bool live = (wq.x + wq.y + wq.z + wq.w) != 0.0f;
            int baseV = v * NP;
            s_off[j][v] = live ? make_int4((baseV + yc0 * SS + xc0) * 8,
                                           (baseV + yc0 * SS + xc1) * 8,
                                           (baseV + yc1 * SS + xc0) * 8,
                                           (baseV + yc1 * SS + xc1) * 8)
                               : make_int4(0, 0, 0, 0);
            s_w[j][v] = wq;
        }
    }
    __syncthreads();

    int j = t >> 3;
    int i = vb + j;
    int ck = t & 7;           // channel chunk (8 channels)
    if (i >= n) return;

    const uint4* B = (const uint4*)g_featT;
    float acc[8] = {0.f,0.f,0.f,0.f,0.f,0.f,0.f,0.f};
    #pragma unroll
    for (int vp = 0; vp < 2; vp++) {
        uint4 r[8];
        int4   o0 = s_off[j][vp*2],   o1 = s_off[j][vp*2+1];
        float4 w0 = s_w[j][vp*2],     w1 = s_w[j][vp*2+1];
        r[0] = B[o0.x + ck]; r[1] = B[o0.y + ck];
        r[2] = B[o0.z + ck]; r[3] = B[o0.w + ck];
        r[4] = B[o1.x + ck]; r[5] = B[o1.y + ck];
        r[6] = B[o1.z + ck]; r[7] = B[o1.w + ck];
        accum8(acc, r[0], w0.x); accum8(acc, r[1], w0.y);
        accum8(acc, r[2], w0.z); accum8(acc, r[3], w0.w);
        accum8(acc, r[4], w1.x); accum8(acc, r[5], w1.y);
        accum8(acc, r[6], w1.z); accum8(acc, r[7], w1.w);
    }
    float4* O = (float4*)(out + (size_t)i * CC + ck * 8);
    __stcs(O,     make_float4(acc[0], acc[1], acc[2], acc[3]));
    __stcs(O + 1, make_float4(acc[4], acc[5], acc[6], acc[7]));
}

// ---------------------------------------------------------------------------
// Side stream + fork/join events: created once (first call is the uncaptured
// correctness run); reused on every call so captured work is identical.
static cudaStream_t g_side = nullptr;
static cudaEvent_t  g_evFork = nullptr, g_evJoin = nullptr;

extern "C" void kernel_launch(void* const* d_in, const int* in_sizes, int n_in,
                              void* d_out, int out_size) {
    const float* verts = nullptr;
    const int*   faces = nullptr;
    const float* Rm = nullptr, *tm = nullptr, *Km = nullptr, *feat = nullptr;
    const int*   p2f = nullptr;
    int n36 = 0;
    for (int i = 0; i < n_in; i++) {
        int s = in_sizes[i];
        if      (s == 600000)   verts = (const float*)d_in[i];
        else if (s == 200000)   faces = (const int*)d_in[i];
        else if (s == 36)       { if (n36++ == 0) Rm = (const float*)d_in[i]; else Km = (const float*)d_in[i]; }
        else if (s == 12)       tm = (const float*)d_in[i];
        else if (s == 67108864) feat = (const float*)d_in[i];
        else if (s == 1048576)  p2f = (const int*)d_in[i];
    }
    int n = 200000;

    if (g_side == nullptr) {
        cudaStreamCreateWithFlags(&g_side, cudaStreamNonBlocking);
        cudaEventCreateWithFlags(&g_evFork, cudaEventDisableTiming);
        cudaEventCreateWithFlags(&g_evJoin, cudaEventDisableTiming);
    }

    // fork: side branch handles visibility + camera (independent of feature)
    cudaEventRecord(g_evFork, 0);
    cudaStreamWaitEvent(g_side, g_evFork, 0);
    clear_vis_kernel<<<(VV * VW + 255) / 256, 256, 0, g_side>>>();
    scatter_vis_kernel<<<(VV * NP + 255) / 256, 256, 0, g_side>>>(p2f);
    cam_kernel<<<1, 32, 0, g_side>>>(Rm, tm, Km);
    cudaEventRecord(g_evJoin, g_side);

    // main branch: full feature transpose (the long pole, at the LTS cap)
    transpose_feat_kernel<<<dim3(NP / 32, VV), 256>>>(feat);

    // join: gather needs featT + vis + P
    cudaStreamWaitEvent(0, g_evJoin, 0);
    gather_kernel<<<(n + 31) / 32, 256>>>((float*)d_out, verts, faces, n);
}